// round 2
// baseline (speedup 1.0000x reference)
#include <cuda_runtime.h>
#include <cuda_bf16.h>

#define NMAX 4096
#define BIGF 1e30f

// Scratch (no allocation allowed -> __device__ globals)
__device__ float4 g_rows[NMAX];        // reflected points + penR (m1 ? 0 : BIG)
__device__ float4 g_cols[NMAX];        // original points  + penC (m2 ? 0 : BIG)
__device__ unsigned int g_d1[NMAX];    // min over m1 rows, per column j (float bits)
__device__ unsigned int g_d2[NMAX];    // min over m2 cols, per row i    (float bits)

// ---------------------------------------------------------------------------
// K1: per-point prep. Reflect across plane, build masks-as-penalties, init mins.
// ---------------------------------------------------------------------------
__global__ void prep_kernel(const float* __restrict__ norm,
                            const float* __restrict__ pts, int n) {
    int i = blockIdx.x * blockDim.x + threadIdx.x;
    if (i >= n) return;
    float nx = norm[0], ny = norm[1], nz = norm[2], d = norm[3];
    float nn = nx * nx + ny * ny + nz * nz;
    float px = pts[3 * i], py = pts[3 * i + 1], pz = pts[3 * i + 2];
    float two_side = -2.0f * (px * nx + py * ny + pz * nz + d);
    float k = two_side / nn;
    bool m1 = two_side > 0.0f;
    g_rows[i] = make_float4(fmaf(k, nx, px), fmaf(k, ny, py), fmaf(k, nz, pz),
                            m1 ? 0.0f : BIGF);
    g_cols[i] = make_float4(px, py, pz, m1 ? BIGF : 0.0f);
    g_d1[i] = __float_as_uint(BIGF);
    g_d2[i] = __float_as_uint(BIGF);
}

// ---------------------------------------------------------------------------
// K2: tiled pairwise distances with masked row/col mins.
// 128x128 tile per block, 256 threads (16x16), 8x8 register micro-tile.
// Thread (ty,tx): rows i0 + ty*8 + r  (r=0..7),  cols j0 + c*16 + tx (c=0..7).
// ---------------------------------------------------------------------------
__global__ void __launch_bounds__(256) dist_kernel(int n) {
    __shared__ float4 sr[128];
    __shared__ float4 sc[128];
    __shared__ unsigned int credu[128];
    __shared__ unsigned int rredu[128];

    int t = threadIdx.x;
    int i0 = blockIdx.y * 128;
    int j0 = blockIdx.x * 128;

    if (t < 128) {
        int gi = i0 + t;
        sr[t] = (gi < n) ? g_rows[gi] : make_float4(0.f, 0.f, 0.f, BIGF);
        credu[t] = __float_as_uint(BIGF);
    } else {
        int u = t - 128;
        int gj = j0 + u;
        sc[u] = (gj < n) ? g_cols[gj] : make_float4(0.f, 0.f, 0.f, BIGF);
        rredu[u] = __float_as_uint(BIGF);
    }
    __syncthreads();

    int tx = t & 15, ty = t >> 4;

    float rx[8], ry[8], rz[8], rp[8];
    float cx[8], cy[8], cz[8], cp[8];
#pragma unroll
    for (int r = 0; r < 8; r++) {
        float4 v = sr[ty * 8 + r];
        rx[r] = v.x; ry[r] = v.y; rz[r] = v.z; rp[r] = v.w;
    }
#pragma unroll
    for (int c = 0; c < 8; c++) {
        float4 v = sc[c * 16 + tx];   // consecutive tx -> conflict-free
        cx[c] = v.x; cy[c] = v.y; cz[c] = v.z; cp[c] = v.w;
    }

    float cmin[8], rmin[8];
#pragma unroll
    for (int k = 0; k < 8; k++) { cmin[k] = BIGF; rmin[k] = BIGF; }

#pragma unroll
    for (int r = 0; r < 8; r++) {
#pragma unroll
        for (int c = 0; c < 8; c++) {
            float dx = rx[r] - cx[c];
            float dy = ry[r] - cy[c];
            float dz = rz[r] - cz[c];
            float D = fmaf(dz, dz, fmaf(dy, dy, dx * dx));
            cmin[c] = fminf(cmin[c], D + rp[r]);  // only m1 rows contribute
            rmin[r] = fminf(rmin[r], D + cp[c]);  // only m2 cols contribute
        }
    }

#pragma unroll
    for (int c = 0; c < 8; c++)
        atomicMin(&credu[c * 16 + tx], __float_as_uint(cmin[c]));
#pragma unroll
    for (int r = 0; r < 8; r++)
        atomicMin(&rredu[ty * 8 + r], __float_as_uint(rmin[r]));
    __syncthreads();

    if (t < 128) {
        int gj = j0 + t;
        if (gj < n) atomicMin(&g_d1[gj], credu[t]);
    } else {
        int u = t - 128;
        int gi = i0 + u;
        if (gi < n) atomicMin(&g_d2[gi], rredu[u]);
    }
}

// ---------------------------------------------------------------------------
// K3: final masked means + scalar output.
// ---------------------------------------------------------------------------
__global__ void reduce_kernel(float* __restrict__ out, int n) {
    int t = threadIdx.x;  // 256 threads, single block
    float s1 = 0.f, s2 = 0.f, c1 = 0.f, c2 = 0.f;
    for (int i = t; i < n; i += 256) {
        float penR = g_rows[i].w;  // 0 iff m1
        float penC = g_cols[i].w;  // 0 iff m2
        float d1 = __uint_as_float(g_d1[i]);
        float d2 = __uint_as_float(g_d2[i]);
        if (penC == 0.0f) { s1 += d1; c2 += 1.0f; }
        if (penR == 0.0f) { s2 += d2; c1 += 1.0f; }
    }
#pragma unroll
    for (int o = 16; o > 0; o >>= 1) {
        s1 += __shfl_xor_sync(0xffffffffu, s1, o);
        s2 += __shfl_xor_sync(0xffffffffu, s2, o);
        c1 += __shfl_xor_sync(0xffffffffu, c1, o);
        c2 += __shfl_xor_sync(0xffffffffu, c2, o);
    }
    __shared__ float sh[4][8];
    int w = t >> 5, l = t & 31;
    if (l == 0) { sh[0][w] = s1; sh[1][w] = s2; sh[2][w] = c1; sh[3][w] = c2; }
    __syncthreads();
    if (t == 0) {
        float S1 = 0.f, S2 = 0.f, C1 = 0.f, C2 = 0.f;
#pragma unroll
        for (int i = 0; i < 8; i++) {
            S1 += sh[0][i]; S2 += sh[1][i]; C1 += sh[2][i]; C2 += sh[3][i];
        }
        C1 = fmaxf(C1, 1.0f);
        C2 = fmaxf(C2, 1.0f);
        out[0] = (0.5f * (S1 / C2) + 0.5f * (S2 / C1)) * 100.0f;
    }
}

// ---------------------------------------------------------------------------
extern "C" void kernel_launch(void* const* d_in, const int* in_sizes, int n_in,
                              void* d_out, int out_size) {
    const float* a0 = (const float*)d_in[0];
    const float* a1 = (const float*)d_in[1];
    const float* norm;
    const float* pts;
    int n;
    if (in_sizes[0] == 4) { norm = a0; pts = a1; n = in_sizes[1] / 3; }
    else                  { norm = a1; pts = a0; n = in_sizes[0] / 3; }

    float* out = (float*)d_out;

    int nb = (n + 255) / 256;
    prep_kernel<<<nb, 256>>>(norm, pts, n);

    int nt = (n + 127) / 128;
    dim3 grid(nt, nt);
    dist_kernel<<<grid, 256>>>(n);

    reduce_kernel<<<1, 256>>>(out, n);
}